// round 13
// baseline (speedup 1.0000x reference)
#include <cuda_runtime.h>
#include <cuda_bf16.h>
#include <cstdint>

#define DIMM 2048
#define NH 16
#define NKV 4
#define HD 128
#define BSZ 2
#define SEQL 4096
#define MTOT (BSZ*SEQL)
#define NQKV 3072

typedef __nv_bfloat16 bf16;
typedef __nv_bfloat162 bf162;

// ---- device-global scratch (no cudaMalloc allowed) ----
__device__ float g_q [BSZ*NH *SEQL*HD];   // fp32 Q pre-norm [b][h][s][d]
__device__ float g_k [BSZ*NKV*SEQL*HD];   // fp32 K pre-norm
__device__ bf16 gq_hi[BSZ*NH *SEQL*HD], gq_lo[BSZ*NH *SEQL*HD];
__device__ bf16 gk_hi[BSZ*NKV*SEQL*HD], gk_lo[BSZ*NKV*SEQL*HD];
__device__ bf16 gv_hi[BSZ*NKV*SEQL*HD], gv_lo[BSZ*NKV*SEQL*HD];
__device__ bf16 gx_hi [MTOT*DIMM], gx_lo [MTOT*DIMM];
__device__ bf16 gw_hi [NQKV*DIMM], gw_lo [NQKV*DIMM];
__device__ bf16 gwo_hi[DIMM*DIMM], gwo_lo[DIMM*DIMM];
__device__ bf16 gao_hi[MTOT*DIMM], gao_lo[MTOT*DIMM];

// =====================================================================
// helpers (sm_80-baseline PTX only: mma.sync / ldmatrix / cp.async)
// =====================================================================
__device__ __forceinline__ uint32_t smem_u32(const void* p) {
    uint32_t a;
    asm("{ .reg .u64 t; cvta.to.shared.u64 t, %1; cvt.u32.u64 %0, t; }"
        : "=r"(a) : "l"(p));
    return a;
}
__device__ __forceinline__ void cpa16(uint32_t s, const void* g) {
    asm volatile("cp.async.cg.shared.global [%0], [%1], 16;" :: "r"(s), "l"(g) : "memory");
}
#define CPA_COMMIT() asm volatile("cp.async.commit_group;" ::: "memory")
#define CPA_WAIT0()  asm volatile("cp.async.wait_group 0;" ::: "memory")
#define CPA_WAIT1()  asm volatile("cp.async.wait_group 1;" ::: "memory")

__device__ __forceinline__ void ldmx4(uint32_t* r, uint32_t a) {
    asm volatile("ldmatrix.sync.aligned.m8n8.x4.shared.b16 {%0,%1,%2,%3}, [%4];"
                 : "=r"(r[0]), "=r"(r[1]), "=r"(r[2]), "=r"(r[3]) : "r"(a));
}
__device__ __forceinline__ void ldmx4t(uint32_t* r, uint32_t a) {
    asm volatile("ldmatrix.sync.aligned.m8n8.x4.trans.shared.b16 {%0,%1,%2,%3}, [%4];"
                 : "=r"(r[0]), "=r"(r[1]), "=r"(r[2]), "=r"(r[3]) : "r"(a));
}
__device__ __forceinline__ void mma16816(float* d, const uint32_t* a,
                                         uint32_t b0, uint32_t b1) {
    asm volatile("mma.sync.aligned.m16n8k16.row.col.f32.bf16.bf16.f32 "
                 "{%0,%1,%2,%3},{%4,%5,%6,%7},{%8,%9},{%0,%1,%2,%3};"
                 : "+f"(d[0]), "+f"(d[1]), "+f"(d[2]), "+f"(d[3])
                 : "r"(a[0]), "r"(a[1]), "r"(a[2]), "r"(a[3]), "r"(b0), "r"(b1));
}
// pack two fp32 -> bf16x2 hi + bf16x2 lo (residual)
__device__ __forceinline__ void split2(float v0, float v1, uint32_t& hi, uint32_t& lo) {
    bf162 h = __floats2bfloat162_rn(v0, v1);
    float r0 = v0 - __bfloat162float(h.x);
    float r1 = v1 - __bfloat162float(h.y);
    bf162 l = __floats2bfloat162_rn(r0, r1);
    hi = *reinterpret_cast<uint32_t*>(&h);
    lo = *reinterpret_cast<uint32_t*>(&l);
}
// swizzled byte offsets (conflict-free ldmatrix)
__device__ __forceinline__ uint32_t offA(int r, int g) {           // 64B rows
    return (uint32_t)(r * 64 + ((g ^ ((r >> 1) & 3)) << 4));
}
__device__ __forceinline__ uint32_t offQ(int r, int g) {           // 256B rows
    return (uint32_t)(r * 256 + ((g ^ (r & 7)) << 4));
}

// =====================================================================
// split: fp32 -> bf16 hi + lo
// =====================================================================
__global__ void split_k(const float* __restrict__ src,
                        bf16* __restrict__ hi, bf16* __restrict__ lo, int n4)
{
    int i = blockIdx.x * blockDim.x + threadIdx.x;
    if (i >= n4) return;
    float4 v = *(const float4*)(src + (size_t)i * 4);
    uint32_t h0, l0, h1, l1;
    split2(v.x, v.y, h0, l0);
    split2(v.z, v.w, h1, l1);
    ((uint32_t*)hi)[2*i] = h0; ((uint32_t*)hi)[2*i+1] = h1;
    ((uint32_t*)lo)[2*i] = l0; ((uint32_t*)lo)[2*i+1] = l1;
}

// =====================================================================
// split-bf16 GEMM via mma.sync: C[m,n] = sum_k A[m,k]*B[n,k]
// CTA 128x128, BK=32, 256 thr, warp grid 2(m)x4(n): warp 64x32.
// DEST 0: q/k fp32 + v split-bf16 scatter.   DEST 1: C fp32 row-major.
// =====================================================================
#define GST 32768   // per stage: Ah 8K | Al 8K | Bh 8K | Bl 8K

template<int DEST>
__global__ void __launch_bounds__(256)
gemm_mma(const bf16* __restrict__ Ah, const bf16* __restrict__ Al,
         const bf16* __restrict__ Bh, const bf16* __restrict__ Bl,
         float* __restrict__ C)
{
    extern __shared__ char smraw[];
    const uint32_t sb = smem_u32(smraw);
    const int t = threadIdx.x, w = t >> 5, L = t & 31;
    const int wm = w >> 2, wn = w & 3;
    const int g = L >> 2, t4 = L & 3;
    const int bm = blockIdx.y * 128, bn = blockIdx.x * 128;

    float acc[4][4][4];
#pragma unroll
    for (int i = 0; i < 4; i++)
#pragma unroll
        for (int j = 0; j < 4; j++)
#pragma unroll
            for (int c = 0; c < 4; c++) acc[i][j][c] = 0.f;

    const int aR = (L & 7) + ((L >> 3) & 1) * 8, aG = L >> 4;
    const int bR = (L & 7) + (L >> 4) * 8,       bG = (L >> 3) & 1;

    auto load_chunk = [&](int ck, int buf) {
        uint32_t st = sb + buf * GST;
        const int kb = ck * 32;
#pragma unroll
        for (int i = 0; i < 2; i++) {
            int gid = i * 256 + t, r = gid >> 2, gg = gid & 3;
            uint32_t off = offA(r, gg);
            size_t goA = (size_t)(bm + r) * DIMM + kb + gg * 8;
            size_t goB = (size_t)(bn + r) * DIMM + kb + gg * 8;
            cpa16(st + off,          Ah + goA);
            cpa16(st + 8192  + off,  Al + goA);
            cpa16(st + 16384 + off,  Bh + goB);
            cpa16(st + 24576 + off,  Bl + goB);
        }
        CPA_COMMIT();
    };

    load_chunk(0, 0);
    for (int ck = 0; ck < 64; ck++) {
        if (ck + 1 < 64) { load_chunk(ck + 1, (ck + 1) & 1); CPA_WAIT1(); }
        else             { CPA_WAIT0(); }
        __syncthreads();
        uint32_t st = sb + (ck & 1) * GST;
#pragma unroll
        for (int ks = 0; ks < 2; ks++) {
            uint32_t ah[4][4], al[4][4];
#pragma unroll
            for (int mt = 0; mt < 4; mt++) {
                uint32_t off = offA(wm * 64 + mt * 16 + aR, ks * 2 + aG);
                ldmx4(ah[mt], st + off);
                ldmx4(al[mt], st + 8192 + off);
            }
            uint32_t bh[2][4], bl[2][4];
#pragma unroll
            for (int p = 0; p < 2; p++) {
                uint32_t off = offA(wn * 32 + p * 16 + bR, ks * 2 + bG);
                ldmx4(bh[p], st + 16384 + off);
                ldmx4(bl[p], st + 24576 + off);
            }
#pragma unroll
            for (int mt = 0; mt < 4; mt++)
#pragma unroll
                for (int nt = 0; nt < 4; nt++) {
                    int p = nt >> 1, q2 = (nt & 1) * 2;
                    uint32_t h0 = bh[p][q2], h1 = bh[p][q2+1];
                    uint32_t l0 = bl[p][q2], l1 = bl[p][q2+1];
                    mma16816(acc[mt][nt], ah[mt], h0, h1);
                    mma16816(acc[mt][nt], ah[mt], l0, l1);
                    mma16816(acc[mt][nt], al[mt], h0, h1);
                }
        }
        __syncthreads();
    }

    // epilogue
#pragma unroll
    for (int mt = 0; mt < 4; mt++) {
#pragma unroll
        for (int nt = 0; nt < 4; nt++) {
            int n = bn + wn * 32 + nt * 8 + t4 * 2;
#pragma unroll
            for (int half = 0; half < 2; half++) {
                int m = bm + wm * 64 + mt * 16 + g + half * 8;
                float c0 = acc[mt][nt][half*2], c1 = acc[mt][nt][half*2+1];
                if (DEST == 1) {
                    *(float2*)(C + (size_t)m * DIMM + n) = make_float2(c0, c1);
                } else {
                    int b = m >> 12, s = m & 4095, d = n & 127;
                    if (n < 2048) {
                        float* dst = g_q + (((size_t)(b*NH + (n >> 7)))*SEQL + s)*HD + d;
                        *(float2*)dst = make_float2(c0, c1);
                    } else if (n < 2560) {
                        float* dst = g_k + (((size_t)(b*NKV + ((n-2048) >> 7)))*SEQL + s)*HD + d;
                        *(float2*)dst = make_float2(c0, c1);
                    } else {
                        size_t idx = (((size_t)(b*NKV + ((n-2560) >> 7)))*SEQL + s)*HD + d;
                        uint32_t hi, lo;
                        split2(c0, c1, hi, lo);
                        *(uint32_t*)(gv_hi + idx) = hi;
                        *(uint32_t*)(gv_lo + idx) = lo;
                    }
                }
            }
        }
    }
}

// =====================================================================
// RMSNorm + RoPE: fp32 in -> split bf16 out (q gets 1/sqrt(HD) folded)
// =====================================================================
__global__ void normrope_k(const float* __restrict__ freqs,
                           const float* __restrict__ qw,
                           const float* __restrict__ kw)
{
    int r = blockIdx.x;
    const float* base; const float* w; bf16 *oh, *ol; float sc;
    if (r < BSZ*NH*SEQL) {
        base = g_q + (size_t)r*HD; w = qw;
        oh = gq_hi + (size_t)r*HD; ol = gq_lo + (size_t)r*HD;
        sc = 0.08838834764831845f;           // 1/sqrt(128)
    } else {
        r -= BSZ*NH*SEQL;
        base = g_k + (size_t)r*HD; w = kw;
        oh = gk_hi + (size_t)r*HD; ol = gk_lo + (size_t)r*HD;
        sc = 1.0f;
    }
    int sidx = r & (SEQL - 1);
    int d = threadIdx.x;

    float v = base[d];
    float ss = v * v;
#pragma unroll
    for (int off = 16; off; off >>= 1) ss += __shfl_xor_sync(0xffffffffu, ss, off);
    __shared__ float red[4];
    int lane = d & 31, wi = d >> 5;
    if (lane == 0) red[wi] = ss;
    __syncthreads();
    float tot = red[0] + red[1] + red[2] + red[3];
    float nv = v * rsqrtf(tot * (1.0f/HD) + 1e-6f) * w[d];

    float partner = __shfl_xor_sync(0xffffffffu, nv, 1);
    float co = freqs[sidx*HD + (d & ~1)];
    float si = freqs[sidx*HD + (d & ~1) + 1];
    float outv = ((d & 1) == 0) ? (nv*co - partner*si)
                                : (partner*si + nv*co);
    outv *= sc;
    bf16 h = __float2bfloat16(outv);
    oh[d] = h;
    ol[d] = __float2bfloat16(outv - __bfloat162float(h));
}

// =====================================================================
// Flash attention via mma.sync, split-bf16 3-term, causal, GQA(4).
// CTA: 128 q rows, 8 warps x 16 rows; k-blocks of 64 double-buffered.
// smem: Qh 32K | Ql 32K | 2 x (Kh 16K | Kl 16K | Vh 16K | Vl 16K) = 192K
// =====================================================================
#define ASM_TOT 196608

__global__ void __launch_bounds__(256)
attn_mma()
{
    extern __shared__ char smraw[];
    const uint32_t sb = smem_u32(smraw);
    const int t = threadIdx.x, w = t >> 5, L = t & 31;
    const int g = L >> 2, t4 = L & 3;
    const int qb = 31 - blockIdx.x, h = blockIdx.y, b = blockIdx.z;
    const int kvh = h >> 2;

    const bf16* qhg = gq_hi + ((size_t)(b*NH  + h  )*SEQL + qb*128)*HD;
    const bf16* qlg = gq_lo + ((size_t)(b*NH  + h  )*SEQL + qb*128)*HD;
    const bf16* khg = gk_hi + ((size_t)(b*NKV + kvh)*SEQL)*HD;
    const bf16* klg = gk_lo + ((size_t)(b*NKV + kvh)*SEQL)*HD;
    const bf16* vhg = gv_hi + ((size_t)(b*NKV + kvh)*SEQL)*HD;
    const bf16* vlg = gv_lo + ((size_t)(b*NKV + kvh)*SEQL)*HD;

    const uint32_t sQh = sb, sQl = sb + 32768;

    auto load_kv = [&](int it, int buf) {
        uint32_t st = sb + 65536 + buf * 65536;
        const int base = it * 64;
#pragma unroll
        for (int i = 0; i < 4; i++) {
            int gid = i * 256 + t, r = gid >> 4, gg = gid & 15;
            uint32_t off = offQ(r, gg);
            size_t go = (size_t)(base + r) * HD + gg * 8;
            cpa16(st + off,          khg + go);
            cpa16(st + 16384 + off,  klg + go);
            cpa16(st + 32768 + off,  vhg + go);
            cpa16(st + 49152 + off,  vlg + go);
        }
        CPA_COMMIT();
    };

    // prologue: Q tile + first KV block
#pragma unroll
    for (int i = 0; i < 8; i++) {
        int gid = i * 256 + t, r = gid >> 4, gg = gid & 15;
        uint32_t off = offQ(r, gg);
        size_t go = (size_t)r * HD + gg * 8;
        cpa16(sQh + off, qhg + go);
        cpa16(sQl + off, qlg + go);
    }
    CPA_COMMIT();
    load_kv(0, 0);

    float o[16][4];
#pragma unroll
    for (int nt = 0; nt < 16; nt++)
#pragma unroll
        for (int c = 0; c < 4; c++) o[nt][c] = 0.f;
    float m0 = -1e30f, m1 = -1e30f, l0 = 0.f, l1 = 0.f;

    const int aR = (L & 7) + ((L >> 3) & 1) * 8, aG = L >> 4;   // A / V-trans lanes
    const int bR = (L & 7) + (L >> 4) * 8,       bG = (L >> 3) & 1;
    const int qrow0 = qb*128 + w*16 + g;                         // + 8 for row1
    const int nkb = 2 * qb + 2;

    for (int it = 0; it < nkb; it++) {
        if (it + 1 < nkb) { load_kv(it + 1, (it + 1) & 1); CPA_WAIT1(); }
        else              { CPA_WAIT0(); }
        __syncthreads();
        const uint32_t st  = sb + 65536 + (it & 1) * 65536;
        const uint32_t sKh = st, sKl = st + 16384;
        const uint32_t sVh = st + 32768, sVl = st + 49152;

        // ---- S = Q K^T (3-term) ----
        float s[8][4];
#pragma unroll
        for (int nt = 0; nt < 8; nt++)
#pragma unroll
            for (int c = 0; c < 4; c++) s[nt][c] = 0.f;

#pragma unroll
        for (int ks = 0; ks < 8; ks++) {
            uint32_t qh4[4], ql4[4];
            uint32_t qoff = offQ(w * 16 + aR, ks * 2 + aG);
            ldmx4(qh4, sQh + qoff);
            ldmx4(ql4, sQl + qoff);
            uint32_t kh4[4][4], kl4[4][4];
#pragma unroll
            for (int p = 0; p < 4; p++) {
                uint32_t koff = offQ(p * 16 + bR, ks * 2 + bG);
                ldmx4(kh4[p], sKh + koff);
                ldmx4(kl4[p], sKl + koff);
            }
#pragma unroll
            for (int nt = 0; nt < 8; nt++) {
                int p = nt >> 1, q2 = (nt & 1) * 2;
                uint32_t h0 = kh4[p][q2], h1 = kh4[p][q2+1];
                uint32_t l0r = kl4[p][q2], l1r = kl4[p][q2+1];
                mma16816(s[nt], qh4, h0, h1);
                mma16816(s[nt], qh4, l0r, l1r);
                mma16816(s[nt], ql4, h0, h1);
            }
        }

        // ---- causal mask ----
        if (it * 64 + 63 > qrow0) {
#pragma unroll
            for (int nt = 0; nt < 8; nt++) {
                int kse = it * 64 + nt * 8 + 2 * t4;
#pragma unroll
                for (int c = 0; c < 4; c++) {
                    int kk = kse + (c & 1);
                    int qr = qrow0 + ((c & 2) ? 8 : 0);
                    if (kk > qr) s[nt][c] = -1e30f;
                }
            }
        }

        // ---- online softmax (rows g and g+8) ----
        float rm0 = -1e30f, rm1 = -1e30f;
#pragma unroll
        for (int nt = 0; nt < 8; nt++) {
            rm0 = fmaxf(rm0, fmaxf(s[nt][0], s[nt][1]));
            rm1 = fmaxf(rm1, fmaxf(s[nt][2], s[nt][3]));
        }
        rm0 = fmaxf(rm0, __shfl_xor_sync(0xffffffffu, rm0, 1));
        rm0 = fmaxf(rm0, __shfl_xor_sync(0xffffffffu, rm0, 2));
        rm1 = fmaxf(rm1, __shfl_xor_sync(0xffffffffu, rm1, 1));
        rm1 = fmaxf(rm1, __shfl_xor_sync(0xffffffffu, rm1, 2));
        float mn0 = fmaxf(m0, rm0), mn1 = fmaxf(m1, rm1);
        float rs0 = 0.f, rs1 = 0.f;
#pragma unroll
        for (int nt = 0; nt < 8; nt++) {
            s[nt][0] = __expf(s[nt][0] - mn0);
            s[nt][1] = __expf(s[nt][1] - mn0);
            s[nt][2] = __expf(s[nt][2] - mn1);
            s[nt][3] = __expf(s[nt][3] - mn1);
            rs0 += s[nt][0] + s[nt][1];
            rs1 += s[nt][2] + s[nt][3];
        }
        rs0 += __shfl_xor_sync(0xffffffffu, rs0, 1);
        rs0 += __shfl_xor_sync(0xffffffffu, rs0, 2);
        rs1 += __shfl_xor_sync(0xffffffffu, rs1, 1);
        rs1 += __shfl_xor_sync(0xffffffffu, rs1, 2);
        float al0 = __expf(m0 - mn0), al1 = __expf(m1 - mn1);
        l0 = l0 * al0 + rs0;  m0 = mn0;
        l1 = l1 * al1 + rs1;  m1 = mn1;
#pragma unroll
        for (int nt = 0; nt < 16; nt++) {
            o[nt][0] *= al0; o[nt][1] *= al0;
            o[nt][2] *= al1; o[nt][3] *= al1;
        }

        // ---- P -> split-bf16 A-fragments (register-resident) ----
        uint32_t pah[4][4], pal[4][4];
#pragma unroll
        for (int kk = 0; kk < 4; kk++) {
            split2(s[2*kk  ][0], s[2*kk  ][1], pah[kk][0], pal[kk][0]);
            split2(s[2*kk  ][2], s[2*kk  ][3], pah[kk][1], pal[kk][1]);
            split2(s[2*kk+1][0], s[2*kk+1][1], pah[kk][2], pal[kk][2]);
            split2(s[2*kk+1][2], s[2*kk+1][3], pah[kk][3], pal[kk][3]);
        }

        // ---- O += P V (3-term; V via ldmatrix.trans) ----
#pragma unroll
        for (int kk = 0; kk < 4; kk++) {
#pragma unroll
            for (int vt = 0; vt < 8; vt++) {
                uint32_t voff = offQ(kk * 16 + aR, vt * 2 + aG);
                uint32_t vh4[4], vl4[4];
                ldmx4t(vh4, sVh + voff);
                ldmx4t(vl4, sVl + voff);
                mma16816(o[vt*2],   pah[kk], vh4[0], vh4[1]);
                mma16816(o[vt*2],   pah[kk], vl4[0], vl4[1]);
                mma16816(o[vt*2],   pal[kk], vh4[0], vh4[1]);
                mma16816(o[vt*2+1], pah[kk], vh4[2], vh4[3]);
                mma16816(o[vt*2+1], pah[kk], vl4[2], vl4[3]);
                mma16816(o[vt*2+1], pal[kk], vh4[2], vh4[3]);
            }
        }
        __syncthreads();
    }

    // ---- epilogue: scale by 1/l, write split-bf16 O ----
    float inv0 = 1.0f / l0, inv1 = 1.0f / l1;
    const int row0 = qrow0, row1 = qrow0 + 8;
    size_t base0 = ((size_t)(b*SEQL + row0))*DIMM + h*HD;
    size_t base1 = ((size_t)(b*SEQL + row1))*DIMM + h*HD;
#pragma unroll
    for (int nt = 0; nt < 16; nt++) {
        int d = nt * 8 + 2 * t4;
        uint32_t hi, lo;
        split2(o[nt][0]*inv0, o[nt][1]*inv0, hi, lo);
        *(uint32_t*)(gao_hi + base0 + d) = hi;
        *(uint32_t*)(gao_lo + base0 + d) = lo;
        split2(o[nt][2]*inv1, o[nt][3]*inv1, hi, lo);
        *(uint32_t*)(gao_hi + base1 + d) = hi;
        *(uint32_t*)(gao_lo + base1 + d) = lo;
    }
}

// =====================================================================
extern "C" void kernel_launch(void* const* d_in, const int* in_sizes, int n_in,
                              void* d_out, int out_size)
{
    const float* x     = (const float*)d_in[0];
    const float* freqs = (const float*)d_in[1];
    const float* wq    = (const float*)d_in[2];
    const float* wk    = (const float*)d_in[3];
    const float* wv    = (const float*)d_in[4];
    const float* wo    = (const float*)d_in[5];
    const float* qnw   = (const float*)d_in[6];
    const float* knw   = (const float*)d_in[7];
    float* out = (float*)d_out;

    void *pxh, *pxl, *pwh, *pwl, *pwoh, *pwol, *paoh, *paol;
    cudaGetSymbolAddress(&pxh,  gx_hi);  cudaGetSymbolAddress(&pxl,  gx_lo);
    cudaGetSymbolAddress(&pwh,  gw_hi);  cudaGetSymbolAddress(&pwl,  gw_lo);
    cudaGetSymbolAddress(&pwoh, gwo_hi); cudaGetSymbolAddress(&pwol, gwo_lo);
    cudaGetSymbolAddress(&paoh, gao_hi); cudaGetSymbolAddress(&paol, gao_lo);
    auto bf = [](void* p) { return (bf16*)p; };

    // splits
    {
        int n4 = MTOT*DIMM/4;
        split_k<<<(n4+255)/256, 256>>>(x, bf(pxh), bf(pxl), n4);
        int nq4 = 2048*DIMM/4, nk4 = 512*DIMM/4;
        split_k<<<(nq4+255)/256, 256>>>(wq, bf(pwh),           bf(pwl),           nq4);
        split_k<<<(nk4+255)/256, 256>>>(wk, bf(pwh)+2048*DIMM, bf(pwl)+2048*DIMM, nk4);
        split_k<<<(nk4+255)/256, 256>>>(wv, bf(pwh)+2560*DIMM, bf(pwl)+2560*DIMM, nk4);
        int no4 = DIMM*DIMM/4;
        split_k<<<(no4+255)/256, 256>>>(wo, bf(pwoh), bf(pwol), no4);
    }

    // fused QKV projection (tensor cores, split-bf16)
    cudaFuncSetAttribute(gemm_mma<0>, cudaFuncAttributeMaxDynamicSharedMemorySize, 2*GST);
    cudaFuncSetAttribute(gemm_mma<1>, cudaFuncAttributeMaxDynamicSharedMemorySize, 2*GST);
    gemm_mma<0><<<dim3(NQKV/128, MTOT/128), 256, 2*GST>>>(bf(pxh), bf(pxl), bf(pwh), bf(pwl), nullptr);

    // RMSNorm + RoPE -> split-bf16 q/k
    normrope_k<<<BSZ*(NH+NKV)*SEQL, 128>>>(freqs, qnw, knw);

    // flash attention (tensor cores)
    cudaFuncSetAttribute(attn_mma, cudaFuncAttributeMaxDynamicSharedMemorySize, ASM_TOT);
    attn_mma<<<dim3(32, NH, BSZ), 256, ASM_TOT>>>();

    // WO projection
    gemm_mma<1><<<dim3(DIMM/128, MTOT/128), 256, 2*GST>>>(bf(paoh), bf(paol), bf(pwoh), bf(pwol), out);
}

// round 14
// speedup vs baseline: 1.0009x; 1.0009x over previous
#include <cuda_runtime.h>
#include <cuda_bf16.h>
#include <cstdint>

#define DIMM 2048
#define NH 16
#define NKV 4
#define HD 128
#define BSZ 2
#define SEQL 4096
#define MTOT (BSZ*SEQL)
#define NQKV 3072

typedef __nv_bfloat16 bf16;
typedef __nv_bfloat162 bf162;

// ---- device-global scratch (no cudaMalloc allowed) ----
__device__ float g_q [BSZ*NH *SEQL*HD];   // fp32 Q pre-norm [b][h][s][d]
__device__ float g_k [BSZ*NKV*SEQL*HD];   // fp32 K pre-norm
__device__ bf16 gq_hi[BSZ*NH *SEQL*HD], gq_lo[BSZ*NH *SEQL*HD];
__device__ bf16 gk_hi[BSZ*NKV*SEQL*HD], gk_lo[BSZ*NKV*SEQL*HD];
__device__ bf16 gv_hi[BSZ*NKV*SEQL*HD], gv_lo[BSZ*NKV*SEQL*HD];
__device__ bf16 gx_hi [MTOT*DIMM], gx_lo [MTOT*DIMM];
__device__ bf16 gw_hi [NQKV*DIMM], gw_lo [NQKV*DIMM];
__device__ bf16 gwo_hi[DIMM*DIMM], gwo_lo[DIMM*DIMM];
__device__ bf16 gao_hi[MTOT*DIMM], gao_lo[MTOT*DIMM];

// =====================================================================
// helpers (sm_80-baseline PTX only: mma.sync / ldmatrix / cp.async)
// =====================================================================
__device__ __forceinline__ uint32_t smem_u32(const void* p) {
    uint32_t a;
    asm("{ .reg .u64 t; cvta.to.shared.u64 t, %1; cvt.u32.u64 %0, t; }"
        : "=r"(a) : "l"(p));
    return a;
}
__device__ __forceinline__ void cpa16(uint32_t s, const void* g) {
    asm volatile("cp.async.cg.shared.global [%0], [%1], 16;" :: "r"(s), "l"(g) : "memory");
}
#define CPA_COMMIT() asm volatile("cp.async.commit_group;" ::: "memory")
#define CPA_WAIT0()  asm volatile("cp.async.wait_group 0;" ::: "memory")
#define CPA_WAIT1()  asm volatile("cp.async.wait_group 1;" ::: "memory")

__device__ __forceinline__ void ldmx4(uint32_t* r, uint32_t a) {
    asm volatile("ldmatrix.sync.aligned.m8n8.x4.shared.b16 {%0,%1,%2,%3}, [%4];"
                 : "=r"(r[0]), "=r"(r[1]), "=r"(r[2]), "=r"(r[3]) : "r"(a));
}
__device__ __forceinline__ void ldmx4t(uint32_t* r, uint32_t a) {
    asm volatile("ldmatrix.sync.aligned.m8n8.x4.trans.shared.b16 {%0,%1,%2,%3}, [%4];"
                 : "=r"(r[0]), "=r"(r[1]), "=r"(r[2]), "=r"(r[3]) : "r"(a));
}
__device__ __forceinline__ void mma16816(float* d, const uint32_t* a,
                                         uint32_t b0, uint32_t b1) {
    asm volatile("mma.sync.aligned.m16n8k16.row.col.f32.bf16.bf16.f32 "
                 "{%0,%1,%2,%3},{%4,%5,%6,%7},{%8,%9},{%0,%1,%2,%3};"
                 : "+f"(d[0]), "+f"(d[1]), "+f"(d[2]), "+f"(d[3])
                 : "r"(a[0]), "r"(a[1]), "r"(a[2]), "r"(a[3]), "r"(b0), "r"(b1));
}
// pack two fp32 -> bf16x2 hi + bf16x2 lo (residual)
__device__ __forceinline__ void split2(float v0, float v1, uint32_t& hi, uint32_t& lo) {
    bf162 h = __floats2bfloat162_rn(v0, v1);
    float r0 = v0 - __bfloat162float(h.x);
    float r1 = v1 - __bfloat162float(h.y);
    bf162 l = __floats2bfloat162_rn(r0, r1);
    hi = *reinterpret_cast<uint32_t*>(&h);
    lo = *reinterpret_cast<uint32_t*>(&l);
}
// swizzled byte offsets (conflict-free ldmatrix)
__device__ __forceinline__ uint32_t offA(int r, int g) {           // 64B rows
    return (uint32_t)(r * 64 + ((g ^ ((r >> 1) & 3)) << 4));
}
__device__ __forceinline__ uint32_t offQ(int r, int g) {           // 256B rows
    return (uint32_t)(r * 256 + ((g ^ (r & 7)) << 4));
}

// =====================================================================
// split: fp32 -> bf16 hi + lo
// =====================================================================
__global__ void split_k(const float* __restrict__ src,
                        bf16* __restrict__ hi, bf16* __restrict__ lo, int n4)
{
    int i = blockIdx.x * blockDim.x + threadIdx.x;
    if (i >= n4) return;
    float4 v = *(const float4*)(src + (size_t)i * 4);
    uint32_t h0, l0, h1, l1;
    split2(v.x, v.y, h0, l0);
    split2(v.z, v.w, h1, l1);
    ((uint32_t*)hi)[2*i] = h0; ((uint32_t*)hi)[2*i+1] = h1;
    ((uint32_t*)lo)[2*i] = l0; ((uint32_t*)lo)[2*i+1] = l1;
}

// =====================================================================
// split-bf16 GEMM via mma.sync: C[m,n] = sum_k A[m,k]*B[n,k]
// CTA 128x128, BK=32, 256 thr, warp grid 2(m)x4(n): warp 64x32.
// DEST 0: q/k fp32 + v split-bf16 scatter.   DEST 1: C fp32 row-major.
// =====================================================================
#define GST 32768   // per stage: Ah 8K | Al 8K | Bh 8K | Bl 8K

template<int DEST>
__global__ void __launch_bounds__(256)
gemm_mma(const bf16* __restrict__ Ah, const bf16* __restrict__ Al,
         const bf16* __restrict__ Bh, const bf16* __restrict__ Bl,
         float* __restrict__ C)
{
    extern __shared__ char smraw[];
    const uint32_t sb = smem_u32(smraw);
    const int t = threadIdx.x, w = t >> 5, L = t & 31;
    const int wm = w >> 2, wn = w & 3;
    const int g = L >> 2, t4 = L & 3;
    const int bm = blockIdx.y * 128, bn = blockIdx.x * 128;

    float acc[4][4][4];
#pragma unroll
    for (int i = 0; i < 4; i++)
#pragma unroll
        for (int j = 0; j < 4; j++)
#pragma unroll
            for (int c = 0; c < 4; c++) acc[i][j][c] = 0.f;

    const int aR = (L & 7) + ((L >> 3) & 1) * 8, aG = L >> 4;
    const int bR = (L & 7) + (L >> 4) * 8,       bG = (L >> 3) & 1;

    auto load_chunk = [&](int ck, int buf) {
        uint32_t st = sb + buf * GST;
        const int kb = ck * 32;
#pragma unroll
        for (int i = 0; i < 2; i++) {
            int gid = i * 256 + t, r = gid >> 2, gg = gid & 3;
            uint32_t off = offA(r, gg);
            size_t goA = (size_t)(bm + r) * DIMM + kb + gg * 8;
            size_t goB = (size_t)(bn + r) * DIMM + kb + gg * 8;
            cpa16(st + off,          Ah + goA);
            cpa16(st + 8192  + off,  Al + goA);
            cpa16(st + 16384 + off,  Bh + goB);
            cpa16(st + 24576 + off,  Bl + goB);
        }
        CPA_COMMIT();
    };

    load_chunk(0, 0);
    for (int ck = 0; ck < 64; ck++) {
        if (ck + 1 < 64) { load_chunk(ck + 1, (ck + 1) & 1); CPA_WAIT1(); }
        else             { CPA_WAIT0(); }
        __syncthreads();
        uint32_t st = sb + (ck & 1) * GST;
#pragma unroll
        for (int ks = 0; ks < 2; ks++) {
            uint32_t ah[4][4], al[4][4];
#pragma unroll
            for (int mt = 0; mt < 4; mt++) {
                uint32_t off = offA(wm * 64 + mt * 16 + aR, ks * 2 + aG);
                ldmx4(ah[mt], st + off);
                ldmx4(al[mt], st + 8192 + off);
            }
            uint32_t bh[2][4], bl[2][4];
#pragma unroll
            for (int p = 0; p < 2; p++) {
                uint32_t off = offA(wn * 32 + p * 16 + bR, ks * 2 + bG);
                ldmx4(bh[p], st + 16384 + off);
                ldmx4(bl[p], st + 24576 + off);
            }
#pragma unroll
            for (int mt = 0; mt < 4; mt++)
#pragma unroll
                for (int nt = 0; nt < 4; nt++) {
                    int p = nt >> 1, q2 = (nt & 1) * 2;
                    uint32_t h0 = bh[p][q2], h1 = bh[p][q2+1];
                    uint32_t l0 = bl[p][q2], l1 = bl[p][q2+1];
                    mma16816(acc[mt][nt], ah[mt], h0, h1);
                    mma16816(acc[mt][nt], ah[mt], l0, l1);
                    mma16816(acc[mt][nt], al[mt], h0, h1);
                }
        }
        __syncthreads();
    }

    // epilogue
#pragma unroll
    for (int mt = 0; mt < 4; mt++) {
#pragma unroll
        for (int nt = 0; nt < 4; nt++) {
            int n = bn + wn * 32 + nt * 8 + t4 * 2;
#pragma unroll
            for (int half = 0; half < 2; half++) {
                int m = bm + wm * 64 + mt * 16 + g + half * 8;
                float c0 = acc[mt][nt][half*2], c1 = acc[mt][nt][half*2+1];
                if (DEST == 1) {
                    *(float2*)(C + (size_t)m * DIMM + n) = make_float2(c0, c1);
                } else {
                    int b = m >> 12, s = m & 4095, d = n & 127;
                    if (n < 2048) {
                        float* dst = g_q + (((size_t)(b*NH + (n >> 7)))*SEQL + s)*HD + d;
                        *(float2*)dst = make_float2(c0, c1);
                    } else if (n < 2560) {
                        float* dst = g_k + (((size_t)(b*NKV + ((n-2048) >> 7)))*SEQL + s)*HD + d;
                        *(float2*)dst = make_float2(c0, c1);
                    } else {
                        size_t idx = (((size_t)(b*NKV + ((n-2560) >> 7)))*SEQL + s)*HD + d;
                        uint32_t hi, lo;
                        split2(c0, c1, hi, lo);
                        *(uint32_t*)(gv_hi + idx) = hi;
                        *(uint32_t*)(gv_lo + idx) = lo;
                    }
                }
            }
        }
    }
}

// =====================================================================
// RMSNorm + RoPE: fp32 in -> split bf16 out (q gets 1/sqrt(HD) folded)
// =====================================================================
__global__ void normrope_k(const float* __restrict__ freqs,
                           const float* __restrict__ qw,
                           const float* __restrict__ kw)
{
    int r = blockIdx.x;
    const float* base; const float* w; bf16 *oh, *ol; float sc;
    if (r < BSZ*NH*SEQL) {
        base = g_q + (size_t)r*HD; w = qw;
        oh = gq_hi + (size_t)r*HD; ol = gq_lo + (size_t)r*HD;
        sc = 0.08838834764831845f;           // 1/sqrt(128)
    } else {
        r -= BSZ*NH*SEQL;
        base = g_k + (size_t)r*HD; w = kw;
        oh = gk_hi + (size_t)r*HD; ol = gk_lo + (size_t)r*HD;
        sc = 1.0f;
    }
    int sidx = r & (SEQL - 1);
    int d = threadIdx.x;

    float v = base[d];
    float ss = v * v;
#pragma unroll
    for (int off = 16; off; off >>= 1) ss += __shfl_xor_sync(0xffffffffu, ss, off);
    __shared__ float red[4];
    int lane = d & 31, wi = d >> 5;
    if (lane == 0) red[wi] = ss;
    __syncthreads();
    float tot = red[0] + red[1] + red[2] + red[3];
    float nv = v * rsqrtf(tot * (1.0f/HD) + 1e-6f) * w[d];

    float partner = __shfl_xor_sync(0xffffffffu, nv, 1);
    float co = freqs[sidx*HD + (d & ~1)];
    float si = freqs[sidx*HD + (d & ~1) + 1];
    float outv = ((d & 1) == 0) ? (nv*co - partner*si)
                                : (partner*si + nv*co);
    outv *= sc;
    bf16 h = __float2bfloat16(outv);
    oh[d] = h;
    ol[d] = __float2bfloat16(outv - __bfloat162float(h));
}

// =====================================================================
// Flash attention via mma.sync, split-bf16 3-term, causal, GQA(4).
// CTA: 128 q rows, 8 warps x 16 rows; k-blocks of 64 double-buffered.
// smem: Qh 32K | Ql 32K | 2 x (Kh 16K | Kl 16K | Vh 16K | Vl 16K) = 192K
// =====================================================================
#define ASM_TOT 196608

__global__ void __launch_bounds__(256)
attn_mma()
{
    extern __shared__ char smraw[];
    const uint32_t sb = smem_u32(smraw);
    const int t = threadIdx.x, w = t >> 5, L = t & 31;
    const int g = L >> 2, t4 = L & 3;
    const int qb = 31 - blockIdx.x, h = blockIdx.y, b = blockIdx.z;
    const int kvh = h >> 2;

    const bf16* qhg = gq_hi + ((size_t)(b*NH  + h  )*SEQL + qb*128)*HD;
    const bf16* qlg = gq_lo + ((size_t)(b*NH  + h  )*SEQL + qb*128)*HD;
    const bf16* khg = gk_hi + ((size_t)(b*NKV + kvh)*SEQL)*HD;
    const bf16* klg = gk_lo + ((size_t)(b*NKV + kvh)*SEQL)*HD;
    const bf16* vhg = gv_hi + ((size_t)(b*NKV + kvh)*SEQL)*HD;
    const bf16* vlg = gv_lo + ((size_t)(b*NKV + kvh)*SEQL)*HD;

    const uint32_t sQh = sb, sQl = sb + 32768;

    auto load_kv = [&](int it, int buf) {
        uint32_t st = sb + 65536 + buf * 65536;
        const int base = it * 64;
#pragma unroll
        for (int i = 0; i < 4; i++) {
            int gid = i * 256 + t, r = gid >> 4, gg = gid & 15;
            uint32_t off = offQ(r, gg);
            size_t go = (size_t)(base + r) * HD + gg * 8;
            cpa16(st + off,          khg + go);
            cpa16(st + 16384 + off,  klg + go);
            cpa16(st + 32768 + off,  vhg + go);
            cpa16(st + 49152 + off,  vlg + go);
        }
        CPA_COMMIT();
    };

    // prologue: Q tile + first KV block
#pragma unroll
    for (int i = 0; i < 8; i++) {
        int gid = i * 256 + t, r = gid >> 4, gg = gid & 15;
        uint32_t off = offQ(r, gg);
        size_t go = (size_t)r * HD + gg * 8;
        cpa16(sQh + off, qhg + go);
        cpa16(sQl + off, qlg + go);
    }
    CPA_COMMIT();
    load_kv(0, 0);

    float o[16][4];
#pragma unroll
    for (int nt = 0; nt < 16; nt++)
#pragma unroll
        for (int c = 0; c < 4; c++) o[nt][c] = 0.f;
    float m0 = -1e30f, m1 = -1e30f, l0 = 0.f, l1 = 0.f;

    const int aR = (L & 7) + ((L >> 3) & 1) * 8, aG = L >> 4;   // A / V-trans lanes
    const int bR = (L & 7) + (L >> 4) * 8,       bG = (L >> 3) & 1;
    const int qrow0 = qb*128 + w*16 + g;                         // + 8 for row1
    const int nkb = 2 * qb + 2;

    for (int it = 0; it < nkb; it++) {
        if (it + 1 < nkb) { load_kv(it + 1, (it + 1) & 1); CPA_WAIT1(); }
        else              { CPA_WAIT0(); }
        __syncthreads();
        const uint32_t st  = sb + 65536 + (it & 1) * 65536;
        const uint32_t sKh = st, sKl = st + 16384;
        const uint32_t sVh = st + 32768, sVl = st + 49152;

        // ---- S = Q K^T (3-term) ----
        float s[8][4];
#pragma unroll
        for (int nt = 0; nt < 8; nt++)
#pragma unroll
            for (int c = 0; c < 4; c++) s[nt][c] = 0.f;

#pragma unroll
        for (int ks = 0; ks < 8; ks++) {
            uint32_t qh4[4], ql4[4];
            uint32_t qoff = offQ(w * 16 + aR, ks * 2 + aG);
            ldmx4(qh4, sQh + qoff);
            ldmx4(ql4, sQl + qoff);
            uint32_t kh4[4][4], kl4[4][4];
#pragma unroll
            for (int p = 0; p < 4; p++) {
                uint32_t koff = offQ(p * 16 + bR, ks * 2 + bG);
                ldmx4(kh4[p], sKh + koff);
                ldmx4(kl4[p], sKl + koff);
            }
#pragma unroll
            for (int nt = 0; nt < 8; nt++) {
                int p = nt >> 1, q2 = (nt & 1) * 2;
                uint32_t h0 = kh4[p][q2], h1 = kh4[p][q2+1];
                uint32_t l0r = kl4[p][q2], l1r = kl4[p][q2+1];
                mma16816(s[nt], qh4, h0, h1);
                mma16816(s[nt], qh4, l0r, l1r);
                mma16816(s[nt], ql4, h0, h1);
            }
        }

        // ---- causal mask ----
        if (it * 64 + 63 > qrow0) {
#pragma unroll
            for (int nt = 0; nt < 8; nt++) {
                int kse = it * 64 + nt * 8 + 2 * t4;
#pragma unroll
                for (int c = 0; c < 4; c++) {
                    int kk = kse + (c & 1);
                    int qr = qrow0 + ((c & 2) ? 8 : 0);
                    if (kk > qr) s[nt][c] = -1e30f;
                }
            }
        }

        // ---- online softmax (rows g and g+8) ----
        float rm0 = -1e30f, rm1 = -1e30f;
#pragma unroll
        for (int nt = 0; nt < 8; nt++) {
            rm0 = fmaxf(rm0, fmaxf(s[nt][0], s[nt][1]));
            rm1 = fmaxf(rm1, fmaxf(s[nt][2], s[nt][3]));
        }
        rm0 = fmaxf(rm0, __shfl_xor_sync(0xffffffffu, rm0, 1));
        rm0 = fmaxf(rm0, __shfl_xor_sync(0xffffffffu, rm0, 2));
        rm1 = fmaxf(rm1, __shfl_xor_sync(0xffffffffu, rm1, 1));
        rm1 = fmaxf(rm1, __shfl_xor_sync(0xffffffffu, rm1, 2));
        float mn0 = fmaxf(m0, rm0), mn1 = fmaxf(m1, rm1);
        float rs0 = 0.f, rs1 = 0.f;
#pragma unroll
        for (int nt = 0; nt < 8; nt++) {
            s[nt][0] = __expf(s[nt][0] - mn0);
            s[nt][1] = __expf(s[nt][1] - mn0);
            s[nt][2] = __expf(s[nt][2] - mn1);
            s[nt][3] = __expf(s[nt][3] - mn1);
            rs0 += s[nt][0] + s[nt][1];
            rs1 += s[nt][2] + s[nt][3];
        }
        rs0 += __shfl_xor_sync(0xffffffffu, rs0, 1);
        rs0 += __shfl_xor_sync(0xffffffffu, rs0, 2);
        rs1 += __shfl_xor_sync(0xffffffffu, rs1, 1);
        rs1 += __shfl_xor_sync(0xffffffffu, rs1, 2);
        float al0 = __expf(m0 - mn0), al1 = __expf(m1 - mn1);
        l0 = l0 * al0 + rs0;  m0 = mn0;
        l1 = l1 * al1 + rs1;  m1 = mn1;
#pragma unroll
        for (int nt = 0; nt < 16; nt++) {
            o[nt][0] *= al0; o[nt][1] *= al0;
            o[nt][2] *= al1; o[nt][3] *= al1;
        }

        // ---- P -> split-bf16 A-fragments (register-resident) ----
        uint32_t pah[4][4], pal[4][4];
#pragma unroll
        for (int kk = 0; kk < 4; kk++) {
            split2(s[2*kk  ][0], s[2*kk  ][1], pah[kk][0], pal[kk][0]);
            split2(s[2*kk  ][2], s[2*kk  ][3], pah[kk][1], pal[kk][1]);
            split2(s[2*kk+1][0], s[2*kk+1][1], pah[kk][2], pal[kk][2]);
            split2(s[2*kk+1][2], s[2*kk+1][3], pah[kk][3], pal[kk][3]);
        }

        // ---- O += P V (3-term; V via ldmatrix.trans) ----
#pragma unroll
        for (int kk = 0; kk < 4; kk++) {
#pragma unroll
            for (int vt = 0; vt < 8; vt++) {
                uint32_t voff = offQ(kk * 16 + aR, vt * 2 + aG);
                uint32_t vh4[4], vl4[4];
                ldmx4t(vh4, sVh + voff);
                ldmx4t(vl4, sVl + voff);
                mma16816(o[vt*2],   pah[kk], vh4[0], vh4[1]);
                mma16816(o[vt*2],   pah[kk], vl4[0], vl4[1]);
                mma16816(o[vt*2],   pal[kk], vh4[0], vh4[1]);
                mma16816(o[vt*2+1], pah[kk], vh4[2], vh4[3]);
                mma16816(o[vt*2+1], pah[kk], vl4[2], vl4[3]);
                mma16816(o[vt*2+1], pal[kk], vh4[2], vh4[3]);
            }
        }
        __syncthreads();
    }

    // ---- epilogue: scale by 1/l, write split-bf16 O ----
    float inv0 = 1.0f / l0, inv1 = 1.0f / l1;
    const int row0 = qrow0, row1 = qrow0 + 8;
    size_t base0 = ((size_t)(b*SEQL + row0))*DIMM + h*HD;
    size_t base1 = ((size_t)(b*SEQL + row1))*DIMM + h*HD;
#pragma unroll
    for (int nt = 0; nt < 16; nt++) {
        int d = nt * 8 + 2 * t4;
        uint32_t hi, lo;
        split2(o[nt][0]*inv0, o[nt][1]*inv0, hi, lo);
        *(uint32_t*)(gao_hi + base0 + d) = hi;
        *(uint32_t*)(gao_lo + base0 + d) = lo;
        split2(o[nt][2]*inv1, o[nt][3]*inv1, hi, lo);
        *(uint32_t*)(gao_hi + base1 + d) = hi;
        *(uint32_t*)(gao_lo + base1 + d) = lo;
    }
}

// =====================================================================
extern "C" void kernel_launch(void* const* d_in, const int* in_sizes, int n_in,
                              void* d_out, int out_size)
{
    const float* x     = (const float*)d_in[0];
    const float* freqs = (const float*)d_in[1];
    const float* wq    = (const float*)d_in[2];
    const float* wk    = (const float*)d_in[3];
    const float* wv    = (const float*)d_in[4];
    const float* wo    = (const float*)d_in[5];
    const float* qnw   = (const float*)d_in[6];
    const float* knw   = (const float*)d_in[7];
    float* out = (float*)d_out;

    void *pxh, *pxl, *pwh, *pwl, *pwoh, *pwol, *paoh, *paol;
    cudaGetSymbolAddress(&pxh,  gx_hi);  cudaGetSymbolAddress(&pxl,  gx_lo);
    cudaGetSymbolAddress(&pwh,  gw_hi);  cudaGetSymbolAddress(&pwl,  gw_lo);
    cudaGetSymbolAddress(&pwoh, gwo_hi); cudaGetSymbolAddress(&pwol, gwo_lo);
    cudaGetSymbolAddress(&paoh, gao_hi); cudaGetSymbolAddress(&paol, gao_lo);
    auto bf = [](void* p) { return (bf16*)p; };

    // splits
    {
        int n4 = MTOT*DIMM/4;
        split_k<<<(n4+255)/256, 256>>>(x, bf(pxh), bf(pxl), n4);
        int nq4 = 2048*DIMM/4, nk4 = 512*DIMM/4;
        split_k<<<(nq4+255)/256, 256>>>(wq, bf(pwh),           bf(pwl),           nq4);
        split_k<<<(nk4+255)/256, 256>>>(wk, bf(pwh)+2048*DIMM, bf(pwl)+2048*DIMM, nk4);
        split_k<<<(nk4+255)/256, 256>>>(wv, bf(pwh)+2560*DIMM, bf(pwl)+2560*DIMM, nk4);
        int no4 = DIMM*DIMM/4;
        split_k<<<(no4+255)/256, 256>>>(wo, bf(pwoh), bf(pwol), no4);
    }

    // fused QKV projection (tensor cores, split-bf16)
    cudaFuncSetAttribute(gemm_mma<0>, cudaFuncAttributeMaxDynamicSharedMemorySize, 2*GST);
    cudaFuncSetAttribute(gemm_mma<1>, cudaFuncAttributeMaxDynamicSharedMemorySize, 2*GST);
    gemm_mma<0><<<dim3(NQKV/128, MTOT/128), 256, 2*GST>>>(bf(pxh), bf(pxl), bf(pwh), bf(pwl), nullptr);

    // RMSNorm + RoPE -> split-bf16 q/k
    normrope_k<<<BSZ*(NH+NKV)*SEQL, 128>>>(freqs, qnw, knw);

    // flash attention (tensor cores)
    cudaFuncSetAttribute(attn_mma, cudaFuncAttributeMaxDynamicSharedMemorySize, ASM_TOT);
    attn_mma<<<dim3(32, NH, BSZ), 256, ASM_TOT>>>();

    // WO projection
    gemm_mma<1><<<dim3(DIMM/128, MTOT/128), 256, 2*GST>>>(bf(paoh), bf(paol), bf(pwoh), bf(pwol), out);
}